// round 17
// baseline (speedup 1.0000x reference)
#include <cuda_runtime.h>

// SoftNCutsLoss: H=W=D=16, P=4096, K=4, RADIUS=5, O_I=10, O_X=4, N=2, C=1.
//
// W[p,q] = mask(sqd<=25) * exp(-(I_p-I_q)^2/10) * exp(-sqd/4)   (symmetric)
// num_k = sum_pq W A_k[p] A_k[q];  den_k = sum_pq W A_k[q]
// out[n] = 4 - sum_k num_k/(den_k+1e-8)
//
// R15: __launch_bounds__(256, 1). Dynamic smem (80KB) already caps us at
// 1-2 blocks/SM, but ptxas can't see it and was register-throttling to 62
// regs -> only ~2 of the 20 exposed load chains in flight (issue% pinned at
// 26-30% across R5-R14). minBlocks=1 frees the register budget so the
// 4-voxel ILP actually pipelines. Ap loads moved AFTER the loop (they're
// epilogue-only; holding them cost 16 persistent regs during the loop).

#define P_VOX    4096
#define K_LAB    4
#define NGROUP   18
#define GSIZE    15            // 18 * 15 = 270 >= 257
#define NOFF_PAD (NGROUP * GSIZE)
#define NBLK_X   4             // 1024-voxel chunks
#define NBATCH   2
#define BLK_PER_N (NGROUP * NBLK_X)               // 72
#define TOTAL_BLOCKS (BLK_PER_N * NBATCH)         // 144

#define SMEM_I_BYTES 16384
#define SMEM_A_BYTES 65536
#define SMEM_BYTES   (SMEM_I_BYTES + SMEM_A_BYTES + 512)

// ---------------------------------------------------------------------------
// Compile-time half-space offset table.
// ---------------------------------------------------------------------------
struct TabT {
    int   x[NOFF_PAD], y[NOFF_PAD], z[NOFF_PAD], dq[NOFF_PAD];
    float c[NOFF_PAD];   // -sqd/4 * log2(e)
};

constexpr TabT gen_tab() {
    TabT t{};
    int cnt = 0;
    for (int dx = 0; dx <= 5; ++dx)
        for (int dy = -5; dy <= 5; ++dy)
            for (int dz = -5; dz <= 5; ++dz) {
                int sq = dx*dx + dy*dy + dz*dz;
                if (sq == 0 || sq > 25) continue;
                bool pos = (dx > 0) || (dx == 0 && (dy > 0 || (dy == 0 && dz > 0)));
                if (!pos) continue;
                t.x[cnt] = dx; t.y[cnt] = dy; t.z[cnt] = dz;
                t.dq[cnt] = dx * 256 + dy * 16 + dz;
                t.c[cnt] = -0.25f * 1.4426950408889634f * (float)sq;
                ++cnt;
            }
    for (; cnt < NOFF_PAD; ++cnt) {     // pad: always out-of-bounds
        t.x[cnt] = 100; t.y[cnt] = 0; t.z[cnt] = 0; t.dq[cnt] = 0; t.c[cnt] = 0.0f;
    }
    return t;
}

constexpr TabT h_tab = gen_tab();
__constant__ TabT c_tab = h_tab;

__device__ float    g_part[TOTAL_BLOCKS * 8];  // overwritten every run
__device__ unsigned g_ctr;                     // atomicInc wraps -> self-reset

// ---------------------------------------------------------------------------
__global__ __launch_bounds__(256, 1)
void sncut_kernel(const float* __restrict__ labels,
                  const float* __restrict__ inputs,
                  float* __restrict__ out) {
    extern __shared__ char smem[];
    float* sI   = (float*)smem;
    float* sA0  = (float*)(smem + SMEM_I_BYTES);   // planar planes
    float* sA1  = sA0 + P_VOX;
    float* sA2  = sA1 + P_VOX;
    float* sA3  = sA2 + P_VOX;
    float* sRed = (float*)(smem + SMEM_I_BYTES + SMEM_A_BYTES);
    __shared__ bool isLast;

    const int tid = threadIdx.x;
    const int n   = blockIdx.y;
    const float* I = inputs + n * P_VOX;
    const float* A = labels + n * K_LAB * P_VOX;

    // Stage I + A (planar, coalesced, conflict-free)
    {
        const float4* I4  = (const float4*)I;
        const float4* A4  = (const float4*)A;
        float4*       sI4 = (float4*)sI;
        float4*       sA4 = (float4*)sA0;
        #pragma unroll
        for (int i = 0; i < 4; ++i)
            sI4[tid + i * 256] = I4[tid + i * 256];
        #pragma unroll
        for (int i = 0; i < 16; ++i)
            sA4[tid + i * 256] = A4[tid + i * 256];
    }
    __syncthreads();

    // 4 voxels per thread: p0 + vx*256, x = 4*chunk + vx (uniform per block).
    const int p0 = (blockIdx.x << 10) + tid;
    const int z  = tid & 15, y = (tid >> 4) & 15;
    const int x0 = blockIdx.x << 2;                 // uniform per block
    const float C2 = -0.14426950408889634f;         // -0.1 * log2(e)

    float Ip[4], rs[4], sk[4][4];
    #pragma unroll
    for (int vx = 0; vx < 4; ++vx) {
        Ip[vx] = sI[p0 + (vx << 8)];
        rs[vx] = 0.f;
        sk[vx][0] = sk[vx][1] = sk[vx][2] = sk[vx][3] = 0.f;
    }

    const int base = blockIdx.z * GSIZE;

    #pragma unroll 5
    for (int o = 0; o < GSIZE; ++o) {
        const int dx = c_tab.x[base + o];            // uniform LDC
        const int qy = y + c_tab.y[base + o];
        const int qz = z + c_tab.z[base + o];
        const bool okyz = ((unsigned)(qy | qz) < 16u);   // exact for 0..15
        const int  qx0  = x0 + dx;                       // uniform
        const int  dq   = c_tab.dq[base + o];
        const float cc  = c_tab.c[base + o];

        #pragma unroll
        for (int vx = 0; vx < 4; ++vx) {
            const bool ok = okyz & ((unsigned)(qx0 + vx) < 16u);
            const int  q  = ok ? (p0 + (vx << 8) + dq) : 0;
            float d   = sI[q] - Ip[vx];
            float arg = fmaf(d * d, C2, cc);
            arg = ok ? arg : -10000.0f;              // ex2(-1e4) == 0
            float w;
            asm("ex2.approx.f32 %0, %1;" : "=f"(w) : "f"(arg));
            rs[vx] += w;
            sk[vx][0] = fmaf(w, sA0[q], sk[vx][0]);
            sk[vx][1] = fmaf(w, sA1[q], sk[vx][1]);
            sk[vx][2] = fmaf(w, sA2[q], sk[vx][2]);
            sk[vx][3] = fmaf(w, sA3[q], sk[vx][3]);
        }
    }

    // Per-thread num/den contributions (diagonal only in group 0).
    // Ap loaded here (epilogue-only) so the loop doesn't hold 16 extra regs.
    const float cen = (blockIdx.z == 0) ? 1.0f : 0.0f;
    float v[8] = {0.f, 0.f, 0.f, 0.f, 0.f, 0.f, 0.f, 0.f};
    #pragma unroll
    for (int vx = 0; vx < 4; ++vx) {
        const int p = p0 + (vx << 8);
        const float a0 = sA0[p], a1 = sA1[p], a2 = sA2[p], a3 = sA3[p];
        v[0] += a0 * (2.f * sk[vx][0] + cen * a0);
        v[1] += a1 * (2.f * sk[vx][1] + cen * a1);
        v[2] += a2 * (2.f * sk[vx][2] + cen * a2);
        v[3] += a3 * (2.f * sk[vx][3] + cen * a3);
        v[4] += fmaf(a0, rs[vx], sk[vx][0]) + cen * a0;
        v[5] += fmaf(a1, rs[vx], sk[vx][1]) + cen * a1;
        v[6] += fmaf(a2, rs[vx], sk[vx][2]) + cen * a2;
        v[7] += fmaf(a3, rs[vx], sk[vx][3]) + cen * a3;
    }

    // Warp reduce -> smem -> block partial
    #pragma unroll
    for (int j = 0; j < 8; ++j) {
        #pragma unroll
        for (int off = 16; off; off >>= 1)
            v[j] += __shfl_down_sync(0xffffffffu, v[j], off);
    }
    const int wid = tid >> 5, lane = tid & 31;
    if (lane == 0) {
        #pragma unroll
        for (int j = 0; j < 8; ++j) sRed[wid * 8 + j] = v[j];
    }
    __syncthreads();

    // Per-n-contiguous partial layout: bid = n*72 + gz*NBLK_X + gx
    const int bid = n * BLK_PER_N + blockIdx.z * NBLK_X + blockIdx.x;
    if (tid < 8) {
        float acc = 0.f;
        #pragma unroll
        for (int w8 = 0; w8 < 8; ++w8) acc += sRed[w8 * 8 + tid];
        g_part[bid * 8 + tid] = acc;
        __threadfence();                 // make partial device-visible
    }
    __syncthreads();

    // Last-block-done: atomicInc wraps at TOTAL_BLOCKS-1 -> self-resetting
    if (tid == 0) {
        unsigned old = atomicInc(&g_ctr, TOTAL_BLOCKS - 1);
        isLast = (old == TOTAL_BLOCKS - 1);
    }
    __syncthreads();

    if (isLast) {
        // 16 output scalars (n,j); 16 threads each, width-16 shuffle reduce.
        const int g = tid >> 4, l16 = tid & 15;     // g: 0..15
        const int nn = g >> 3, j = g & 7;
        float acc = 0.f;
        #pragma unroll
        for (int m = l16; m < BLK_PER_N; m += 16)
            acc += __ldcg(&g_part[(nn * BLK_PER_N + m) * 8 + j]);
        #pragma unroll
        for (int off = 8; off; off >>= 1)
            acc += __shfl_down_sync(0xffffffffu, acc, off, 16);
        if (l16 == 0) sRed[64 + g] = acc;
        __syncthreads();
        if (tid < 2) {
            float loss = 0.f;
            #pragma unroll
            for (int k = 0; k < K_LAB; ++k)
                loss += sRed[64 + tid * 8 + k] / (sRed[64 + tid * 8 + 4 + k] + 1e-8f);
            out[tid] = 4.0f - loss;
        }
    }
}

// ---------------------------------------------------------------------------
extern "C" void kernel_launch(void* const* d_in, const int* in_sizes, int n_in,
                              void* d_out, int out_size) {
    // labels = 2*4*4096 = 32768 elems, inputs = 2*1*4096 = 8192 elems
    const float* labels;
    const float* inputs;
    if (in_sizes[0] == 2 * K_LAB * P_VOX) {
        labels = (const float*)d_in[0];
        inputs = (const float*)d_in[1];
    } else {
        labels = (const float*)d_in[1];
        inputs = (const float*)d_in[0];
    }
    float* out = (float*)d_out;

    cudaFuncSetAttribute(sncut_kernel,
                         cudaFuncAttributeMaxDynamicSharedMemorySize, SMEM_BYTES);

    dim3 grid(NBLK_X, NBATCH, NGROUP);
    sncut_kernel<<<grid, 256, SMEM_BYTES>>>(labels, inputs, out);
}